// round 1
// baseline (speedup 1.0000x reference)
#include <cuda_runtime.h>

// Problem constants (B=4, H=16, T=2048, D=64), fp32 in/out.
#define TT      2048
#define DD      64
#define CHUNK   64
#define NC      (TT / CHUNK)   // 32 chunks
#define BHN     64             // B*H
#define PITCH   68             // smem row pitch (floats), 16B-aligned, conflict-tamed
#define NTHREADS 256

// Scratch for per-chunk KV states -> exclusive prefix states. 64*32*64*64 floats = 32 MB.
__device__ float g_state[(size_t)BHN * NC * DD * DD];

// ---------------------------------------------------------------------------
// Kernel 1: per-(bh, chunk) KV_c = K_c^T V_c  [D x D], fully parallel.
// ---------------------------------------------------------------------------
__global__ __launch_bounds__(NTHREADS) void kv_kernel(const float* __restrict__ kg,
                                                      const float* __restrict__ vg) {
    __shared__ float sK[CHUNK][PITCH];
    __shared__ float sV[CHUNK][PITCH];
    const int c = blockIdx.x, bh = blockIdx.y;
    const int tid = threadIdx.x;

    const float* kp = kg + ((size_t)bh * TT + (size_t)c * CHUNK) * DD;
    const float* vp = vg + ((size_t)bh * TT + (size_t)c * CHUNK) * DD;

#pragma unroll
    for (int i = 0; i < (CHUNK * DD) / NTHREADS; i++) {
        int idx = tid + i * NTHREADS;
        int r = idx >> 6, cc = idx & 63;
        sK[r][cc] = kp[idx];
        sV[r][cc] = vp[idx];
    }
    __syncthreads();

    const int ty = tid >> 4, tx = tid & 15;
    const int d0 = ty * 4, e0 = tx * 4;

    float acc[4][4] = {};
#pragma unroll 8
    for (int j = 0; j < CHUNK; j++) {
        float4 av = *(const float4*)&sK[j][d0];
        float4 bv = *(const float4*)&sV[j][e0];
        float a[4] = {av.x, av.y, av.z, av.w};
        float b[4] = {bv.x, bv.y, bv.z, bv.w};
#pragma unroll
        for (int r = 0; r < 4; r++)
#pragma unroll
            for (int cc = 0; cc < 4; cc++)
                acc[r][cc] = fmaf(a[r], b[cc], acc[r][cc]);
    }

    float* outp = g_state + ((size_t)(bh * NC + c)) * (DD * DD);
#pragma unroll
    for (int r = 0; r < 4; r++) {
        float4 val = make_float4(acc[r][0], acc[r][1], acc[r][2], acc[r][3]);
        *(float4*)&outp[(size_t)(d0 + r) * DD + e0] = val;
    }
}

// ---------------------------------------------------------------------------
// Kernel 2: in-place exclusive prefix over the 32 chunk states per (bh).
// Each thread owns one of the 4096 state elements; 32-step serial scan.
// ---------------------------------------------------------------------------
__global__ __launch_bounds__(NTHREADS) void prefix_kernel() {
    const int e = blockIdx.x * NTHREADS + threadIdx.x;  // 0..4095
    const int bh = blockIdx.y;
    size_t base = (size_t)bh * NC * (DD * DD) + e;
    float run = 0.f;
#pragma unroll
    for (int c = 0; c < NC; c++) {
        float t = g_state[base + (size_t)c * (DD * DD)];
        g_state[base + (size_t)c * (DD * DD)] = run;
        run += t;
    }
}

// ---------------------------------------------------------------------------
// Kernel 3: per-(bh, chunk) output:
//   O_c = Q_c @ S_c  +  tril(Q_c @ K_c^T) @ V_c
// ---------------------------------------------------------------------------
__global__ __launch_bounds__(NTHREADS) void out_kernel(const float* __restrict__ qg,
                                                       const float* __restrict__ kg,
                                                       const float* __restrict__ vg,
                                                       float* __restrict__ og) {
    extern __shared__ float sm[];
    float* sQ  = sm;                    // [64][PITCH]
    float* sKT = sm + 1 * CHUNK * PITCH; // transposed: sKT[d][j] = K[j][d]
    float* sV  = sm + 2 * CHUNK * PITCH; // [64][PITCH]
    float* sS  = sm + 3 * CHUNK * PITCH; // [64][PITCH]
    float* sP  = sm + 4 * CHUNK * PITCH; // [64][PITCH]

    const int c = blockIdx.x, bh = blockIdx.y;
    const int tid = threadIdx.x;

    const float* qp = qg + ((size_t)bh * TT + (size_t)c * CHUNK) * DD;
    const float* kp = kg + ((size_t)bh * TT + (size_t)c * CHUNK) * DD;
    const float* vp = vg + ((size_t)bh * TT + (size_t)c * CHUNK) * DD;
    const float* sp = g_state + ((size_t)(bh * NC + c)) * (DD * DD);

#pragma unroll
    for (int i = 0; i < (CHUNK * DD) / NTHREADS; i++) {
        int idx = tid + i * NTHREADS;
        int r = idx >> 6, cc = idx & 63;
        sQ[r * PITCH + cc]  = qp[idx];
        sKT[cc * PITCH + r] = kp[idx];   // transpose K on the way in
        sV[r * PITCH + cc]  = vp[idx];
        sS[r * PITCH + cc]  = sp[idx];
    }
    __syncthreads();

    const int ty = tid >> 4, tx = tid & 15;
    const int i0 = ty * 4;   // output rows
    const int j0 = tx * 4;   // P columns (keys)
    const int e0 = tx * 4;   // output cols (values)

    // ---- Phase B: P = Q K^T with causal mask (local) ----
    float p[4][4] = {};
#pragma unroll 8
    for (int d = 0; d < DD; d++) {
        float qa[4];
#pragma unroll
        for (int r = 0; r < 4; r++) qa[r] = sQ[(i0 + r) * PITCH + d];
        float4 kb4 = *(const float4*)&sKT[d * PITCH + j0];
        float kb[4] = {kb4.x, kb4.y, kb4.z, kb4.w};
#pragma unroll
        for (int r = 0; r < 4; r++)
#pragma unroll
            for (int cc = 0; cc < 4; cc++)
                p[r][cc] = fmaf(qa[r], kb[cc], p[r][cc]);
    }
#pragma unroll
    for (int r = 0; r < 4; r++)
#pragma unroll
        for (int cc = 0; cc < 4; cc++)
            sP[(i0 + r) * PITCH + (j0 + cc)] = ((j0 + cc) <= (i0 + r)) ? p[r][cc] : 0.f;
    __syncthreads();

    // ---- Phase C: O = Q @ S + P @ V ----
    float o[4][4] = {};
#pragma unroll 8
    for (int d = 0; d < DD; d++) {
        float qa[4];
#pragma unroll
        for (int r = 0; r < 4; r++) qa[r] = sQ[(i0 + r) * PITCH + d];
        float4 s4 = *(const float4*)&sS[d * PITCH + e0];
        float s[4] = {s4.x, s4.y, s4.z, s4.w};
#pragma unroll
        for (int r = 0; r < 4; r++)
#pragma unroll
            for (int cc = 0; cc < 4; cc++)
                o[r][cc] = fmaf(qa[r], s[cc], o[r][cc]);
    }
#pragma unroll 8
    for (int j = 0; j < CHUNK; j++) {
        float pa[4];
#pragma unroll
        for (int r = 0; r < 4; r++) pa[r] = sP[(i0 + r) * PITCH + j];
        float4 v4 = *(const float4*)&sV[j * PITCH + e0];
        float vv[4] = {v4.x, v4.y, v4.z, v4.w};
#pragma unroll
        for (int r = 0; r < 4; r++)
#pragma unroll
            for (int cc = 0; cc < 4; cc++)
                o[r][cc] = fmaf(pa[r], vv[cc], o[r][cc]);
    }

    float* op = og + ((size_t)bh * TT + (size_t)c * CHUNK) * DD;
#pragma unroll
    for (int r = 0; r < 4; r++) {
        float4 val = make_float4(o[r][0], o[r][1], o[r][2], o[r][3]);
        *(float4*)&op[(size_t)(i0 + r) * DD + e0] = val;
    }
}

// ---------------------------------------------------------------------------
extern "C" void kernel_launch(void* const* d_in, const int* in_sizes, int n_in,
                              void* d_out, int out_size) {
    const float* q = (const float*)d_in[0];
    const float* k = (const float*)d_in[1];
    const float* v = (const float*)d_in[2];
    float* o = (float*)d_out;

    const int smem3 = 5 * CHUNK * PITCH * (int)sizeof(float);  // 87,040 B
    cudaFuncSetAttribute(out_kernel, cudaFuncAttributeMaxDynamicSharedMemorySize, smem3);

    dim3 gridTiles(NC, BHN);
    kv_kernel<<<gridTiles, NTHREADS>>>(k, v);
    prefix_kernel<<<dim3((DD * DD) / NTHREADS, BHN), NTHREADS>>>();
    out_kernel<<<gridTiles, NTHREADS, smem3>>>(q, k, v, o);
}

// round 3
// speedup vs baseline: 1.0982x; 1.0982x over previous
#include <cuda_runtime.h>
#include <cuda_bf16.h>
#include <cstdint>

#define TT   2048
#define DD   64
#define CH   64
#define NC   (TT/CH)    // 32 chunks
#define BH   64         // B*H
#define PIT  72         // smem tile pitch in bf16 elements (144B rows)

// Exclusive-prefix KV states, fp32: 64 * 32 * 64 * 64 * 4B = 32 MB
__device__ float g_state[(size_t)BH * NC * DD * DD];

// ---------------------------------------------------------------------------
// Warp-level MMA helpers (baseline PTX: sm_80 mma.sync + sm_75 ldmatrix)
// ---------------------------------------------------------------------------
__device__ __forceinline__ uint32_t smem_u32(const void* p) {
    uint32_t a;
    asm("{ .reg .u64 t; cvta.to.shared.u64 t, %1; cvt.u32.u64 %0, t; }" : "=r"(a) : "l"(p));
    return a;
}

__device__ __forceinline__ void ldsm4(uint32_t addr, uint32_t r[4]) {
    asm volatile("ldmatrix.sync.aligned.m8n8.x4.shared.b16 {%0,%1,%2,%3}, [%4];"
                 : "=r"(r[0]), "=r"(r[1]), "=r"(r[2]), "=r"(r[3]) : "r"(addr));
}

__device__ __forceinline__ void mma16816(float c[4], const uint32_t a[4], uint32_t b0, uint32_t b1) {
    asm volatile(
        "mma.sync.aligned.m16n8k16.row.col.f32.bf16.bf16.f32 "
        "{%0,%1,%2,%3}, {%4,%5,%6,%7}, {%8,%9}, {%0,%1,%2,%3};"
        : "+f"(c[0]), "+f"(c[1]), "+f"(c[2]), "+f"(c[3])
        : "r"(a[0]), "r"(a[1]), "r"(a[2]), "r"(a[3]), "r"(b0), "r"(b1));
}

// 64x64x64 GEMM contribution for this warp's 32x32 quadrant.
// A tile: [64][PIT] row-major (m x k). B tile: [64][PIT] row-major = [n][k].
// aBase/bBase already offset to the warp's r0/n0 rows.
__device__ __forceinline__ void wgemm64(uint32_t aBase, uint32_t bBase, float acc[2][4][4]) {
    const int l = threadIdx.x & 31;
    const uint32_t aAddr = aBase + (((uint32_t)(l & 15)) * PIT + (((uint32_t)l >> 4) << 3)) * 2u;
    const uint32_t bAddr = bBase + ((((uint32_t)(l & 7)) + (((uint32_t)l & 16) >> 1)) * PIT
                                    + (((uint32_t)(l >> 3) & 1) << 3)) * 2u;
#pragma unroll
    for (int ks = 0; ks < 4; ks++) {
        const uint32_t kb = ks * 16 * 2;
        uint32_t a0[4], a1[4];
        ldsm4(aAddr + kb, a0);
        ldsm4(aAddr + kb + 16 * PIT * 2, a1);
#pragma unroll
        for (int n2 = 0; n2 < 2; n2++) {
            uint32_t b[4];
            ldsm4(bAddr + kb + n2 * 16 * PIT * 2, b);
            mma16816(acc[0][2 * n2],     a0, b[0], b[1]);
            mma16816(acc[0][2 * n2 + 1], a0, b[2], b[3]);
            mma16816(acc[1][2 * n2],     a1, b[0], b[1]);
            mma16816(acc[1][2 * n2 + 1], a1, b[2], b[3]);
        }
    }
}

__device__ __forceinline__ void split_bf(float x, __nv_bfloat16& h, __nv_bfloat16& l) {
    h = __float2bfloat16(x);
    l = __float2bfloat16(x - __bfloat162float(h));
}
__device__ __forceinline__ uint32_t pack2(__nv_bfloat16 a, __nv_bfloat16 b) {
    __nv_bfloat162 v = __halves2bfloat162(a, b);
    return *reinterpret_cast<uint32_t*>(&v);
}

// ---------------------------------------------------------------------------
// Kernel 1: KV_c = K_c^T V_c  (A = K^T [d][j], B = V^T [e][j])
// ---------------------------------------------------------------------------
#define K1_KTH 0
#define K1_KTL 9216
#define K1_VTH 18432
#define K1_VTL 27648
#define K1_SMEM 36864

__global__ __launch_bounds__(128, 4) void kv_kernel(const float* __restrict__ kg,
                                                    const float* __restrict__ vg) {
    extern __shared__ char sm[];
    const uint32_t sb = smem_u32(sm);
    const int tid = threadIdx.x, w = tid >> 5, l = tid & 31;
    const int c = blockIdx.x, bh = blockIdx.y;

    const float* kp = kg + ((size_t)bh * TT + (size_t)c * CH) * DD;
    const float* vp = vg + ((size_t)bh * TT + (size_t)c * CH) * DD;

#pragma unroll
    for (int it = 0; it < 8; it++) {
        int idx = tid + it * 128;              // float4 idx 0..1023
        int j  = idx >> 4;                     // token
        int d0 = (idx & 15) * 4;               // feature
        float4 k4 = *(const float4*)(kp + (size_t)j * DD + d0);
        float4 v4 = *(const float4*)(vp + (size_t)j * DD + d0);
        float ka[4] = {k4.x, k4.y, k4.z, k4.w};
        float va[4] = {v4.x, v4.y, v4.z, v4.w};
#pragma unroll
        for (int q = 0; q < 4; q++) {
            __nv_bfloat16 h, lo;
            split_bf(ka[q], h, lo);
            *(__nv_bfloat16*)(sm + K1_KTH + ((d0 + q) * PIT + j) * 2) = h;
            *(__nv_bfloat16*)(sm + K1_KTL + ((d0 + q) * PIT + j) * 2) = lo;
            split_bf(va[q], h, lo);
            *(__nv_bfloat16*)(sm + K1_VTH + ((d0 + q) * PIT + j) * 2) = h;
            *(__nv_bfloat16*)(sm + K1_VTL + ((d0 + q) * PIT + j) * 2) = lo;
        }
    }
    __syncthreads();

    const int r0 = (w & 1) * 32, n0 = (w >> 1) * 32;
    float acc[2][4][4] = {};
    wgemm64(sb + K1_KTH + r0 * PIT * 2, sb + K1_VTH + n0 * PIT * 2, acc);
    wgemm64(sb + K1_KTH + r0 * PIT * 2, sb + K1_VTL + n0 * PIT * 2, acc);
    wgemm64(sb + K1_KTL + r0 * PIT * 2, sb + K1_VTH + n0 * PIT * 2, acc);

    float* outp = g_state + ((size_t)(bh * NC + c)) * (DD * DD);
#pragma unroll
    for (int mi = 0; mi < 2; mi++)
#pragma unroll
        for (int ni = 0; ni < 4; ni++)
#pragma unroll
            for (int half = 0; half < 2; half++) {
                int d = r0 + mi * 16 + (l >> 2) + half * 8;
                int e = n0 + ni * 8 + 2 * (l & 3);
                *(float2*)(outp + (size_t)d * DD + e) =
                    make_float2(acc[mi][ni][2 * half], acc[mi][ni][2 * half + 1]);
            }
}

// ---------------------------------------------------------------------------
// Kernel 2: exclusive prefix over 32 chunk states per bh (fp32)
// ---------------------------------------------------------------------------
__global__ __launch_bounds__(256) void prefix_kernel() {
    const int e = blockIdx.x * 256 + threadIdx.x;  // 0..4095
    const int bh = blockIdx.y;
    size_t base = (size_t)bh * NC * (DD * DD) + e;
    float run = 0.f;
#pragma unroll
    for (int c = 0; c < NC; c++) {
        float t = g_state[base + (size_t)c * (DD * DD)];
        g_state[base + (size_t)c * (DD * DD)] = run;
        run += t;
    }
}

// ---------------------------------------------------------------------------
// Kernel 3: P = tril(Q K^T); O = Q S + P V
//   P gemm: A=Q [i][d], B=K [j][d]
//   O gemm: A=Q, B=S^T [e][d];  A=P [i][j], B=V^T [e][j]
// ---------------------------------------------------------------------------
#define K3_QH  0
#define K3_QL  9216
#define K3_KH  18432
#define K3_KL  27648
#define K3_VTH 36864
#define K3_VTL 46080
#define K3_STH 55296
#define K3_STL 64512
#define K3_PH  73728
#define K3_PL  82944
#define K3_SMEM 92160

__global__ __launch_bounds__(128, 2) void out_kernel(const float* __restrict__ qg,
                                                     const float* __restrict__ kg,
                                                     const float* __restrict__ vg,
                                                     float* __restrict__ og) {
    extern __shared__ char sm[];
    const uint32_t sb = smem_u32(sm);
    const int tid = threadIdx.x, w = tid >> 5, l = tid & 31;
    const int c = blockIdx.x, bh = blockIdx.y;

    const float* qp = qg + ((size_t)bh * TT + (size_t)c * CH) * DD;
    const float* kp = kg + ((size_t)bh * TT + (size_t)c * CH) * DD;
    const float* vp = vg + ((size_t)bh * TT + (size_t)c * CH) * DD;
    const float* sp = g_state + ((size_t)(bh * NC + c)) * (DD * DD);

#pragma unroll
    for (int it = 0; it < 8; it++) {
        int idx = tid + it * 128;
        int r  = idx >> 4;
        int d0 = (idx & 15) * 4;
        float4 q4 = *(const float4*)(qp + (size_t)r * DD + d0);
        float4 k4 = *(const float4*)(kp + (size_t)r * DD + d0);
        float4 v4 = *(const float4*)(vp + (size_t)r * DD + d0);
        float4 s4 = *(const float4*)(sp + (size_t)r * DD + d0);
        __nv_bfloat16 h0, l0, h1, l1, h2, l2, h3, l3;
        // Q straight [i][d]
        split_bf(q4.x, h0, l0); split_bf(q4.y, h1, l1);
        split_bf(q4.z, h2, l2); split_bf(q4.w, h3, l3);
        *(uint2*)(sm + K3_QH + (r * PIT + d0) * 2) = make_uint2(pack2(h0, h1), pack2(h2, h3));
        *(uint2*)(sm + K3_QL + (r * PIT + d0) * 2) = make_uint2(pack2(l0, l1), pack2(l2, l3));
        // K straight [j][d]
        split_bf(k4.x, h0, l0); split_bf(k4.y, h1, l1);
        split_bf(k4.z, h2, l2); split_bf(k4.w, h3, l3);
        *(uint2*)(sm + K3_KH + (r * PIT + d0) * 2) = make_uint2(pack2(h0, h1), pack2(h2, h3));
        *(uint2*)(sm + K3_KL + (r * PIT + d0) * 2) = make_uint2(pack2(l0, l1), pack2(l2, l3));
        // V transposed -> VT[e][j]
        float va[4] = {v4.x, v4.y, v4.z, v4.w};
        float sa[4] = {s4.x, s4.y, s4.z, s4.w};
#pragma unroll
        for (int q = 0; q < 4; q++) {
            __nv_bfloat16 h, lo;
            split_bf(va[q], h, lo);
            *(__nv_bfloat16*)(sm + K3_VTH + ((d0 + q) * PIT + r) * 2) = h;
            *(__nv_bfloat16*)(sm + K3_VTL + ((d0 + q) * PIT + r) * 2) = lo;
            // S[d][e] -> ST[e][d]
            split_bf(sa[q], h, lo);
            *(__nv_bfloat16*)(sm + K3_STH + ((d0 + q) * PIT + r) * 2) = h;
            *(__nv_bfloat16*)(sm + K3_STL + ((d0 + q) * PIT + r) * 2) = lo;
        }
    }
    __syncthreads();

    const int r0 = (w & 1) * 32, n0 = (w >> 1) * 32;

    // ---- P = Q K^T (3 split passes) ----
    float acc[2][4][4] = {};
    wgemm64(sb + K3_QH + r0 * PIT * 2, sb + K3_KH + n0 * PIT * 2, acc);
    wgemm64(sb + K3_QH + r0 * PIT * 2, sb + K3_KL + n0 * PIT * 2, acc);
    wgemm64(sb + K3_QL + r0 * PIT * 2, sb + K3_KH + n0 * PIT * 2, acc);

    // mask (j<=i), split, store P tiles
#pragma unroll
    for (int mi = 0; mi < 2; mi++)
#pragma unroll
        for (int ni = 0; ni < 4; ni++)
#pragma unroll
            for (int half = 0; half < 2; half++) {
                int i = r0 + mi * 16 + (l >> 2) + half * 8;
                int j0 = n0 + ni * 8 + 2 * (l & 3);
                float f0 = (j0     <= i) ? acc[mi][ni][2 * half]     : 0.f;
                float f1 = (j0 + 1 <= i) ? acc[mi][ni][2 * half + 1] : 0.f;
                __nv_bfloat16 h0, l0, h1, l1;
                split_bf(f0, h0, l0);
                split_bf(f1, h1, l1);
                *(uint32_t*)(sm + K3_PH + (i * PIT + j0) * 2) = pack2(h0, h1);
                *(uint32_t*)(sm + K3_PL + (i * PIT + j0) * 2) = pack2(l0, l1);
            }
    __syncthreads();

    // ---- O = Q S^T^T + P V : accumulate both ----
    float oac[2][4][4] = {};
    wgemm64(sb + K3_QH + r0 * PIT * 2, sb + K3_STH + n0 * PIT * 2, oac);
    wgemm64(sb + K3_QH + r0 * PIT * 2, sb + K3_STL + n0 * PIT * 2, oac);
    wgemm64(sb + K3_QL + r0 * PIT * 2, sb + K3_STH + n0 * PIT * 2, oac);
    wgemm64(sb + K3_PH + r0 * PIT * 2, sb + K3_VTH + n0 * PIT * 2, oac);
    wgemm64(sb + K3_PH + r0 * PIT * 2, sb + K3_VTL + n0 * PIT * 2, oac);
    wgemm64(sb + K3_PL + r0 * PIT * 2, sb + K3_VTH + n0 * PIT * 2, oac);

    float* op = og + ((size_t)bh * TT + (size_t)c * CH) * DD;
#pragma unroll
    for (int mi = 0; mi < 2; mi++)
#pragma unroll
        for (int ni = 0; ni < 4; ni++)
#pragma unroll
            for (int half = 0; half < 2; half++) {
                int i = r0 + mi * 16 + (l >> 2) + half * 8;
                int e = n0 + ni * 8 + 2 * (l & 3);
                *(float2*)(op + (size_t)i * DD + e) =
                    make_float2(oac[mi][ni][2 * half], oac[mi][ni][2 * half + 1]);
            }
}

// ---------------------------------------------------------------------------
extern "C" void kernel_launch(void* const* d_in, const int* in_sizes, int n_in,
                              void* d_out, int out_size) {
    const float* q = (const float*)d_in[0];
    const float* k = (const float*)d_in[1];
    const float* v = (const float*)d_in[2];
    float* o = (float*)d_out;

    cudaFuncSetAttribute(kv_kernel, cudaFuncAttributeMaxDynamicSharedMemorySize, K1_SMEM);
    cudaFuncSetAttribute(out_kernel, cudaFuncAttributeMaxDynamicSharedMemorySize, K3_SMEM);

    dim3 grid(NC, BH);
    kv_kernel<<<grid, 128, K1_SMEM>>>(k, v);
    prefix_kernel<<<dim3((DD * DD) / 256, BH), 256>>>();
    out_kernel<<<grid, 128, K3_SMEM>>>(q, k, v, o);
}

// round 4
// speedup vs baseline: 1.7940x; 1.6336x over previous
#include <cuda_runtime.h>
#include <cuda_bf16.h>
#include <cstdint>

#define TT   2048
#define DD   64
#define CH   64
#define NC   (TT/CH)    // 32 chunks
#define BH   64         // B*H
#define PIT  72         // smem pitch in bf16 elements (144B rows, ldmatrix conflict-free)
#define TILE_B (DD*PIT*2)  // 9216 bytes per 64x64 bf16 tile

// Exclusive-prefix KV states, fp32: 64 * 32 * 64 * 64 * 4B = 32 MB
__device__ float g_state[(size_t)BH * NC * DD * DD];

// ---------------------------------------------------------------------------
// helpers
// ---------------------------------------------------------------------------
__device__ __forceinline__ uint32_t smem_u32(const void* p) {
    uint32_t a;
    asm("{ .reg .u64 t; cvta.to.shared.u64 t, %1; cvt.u32.u64 %0, t; }" : "=r"(a) : "l"(p));
    return a;
}
__device__ __forceinline__ void ldsm4(uint32_t addr, uint32_t r[4]) {
    asm volatile("ldmatrix.sync.aligned.m8n8.x4.shared.b16 {%0,%1,%2,%3}, [%4];"
                 : "=r"(r[0]), "=r"(r[1]), "=r"(r[2]), "=r"(r[3]) : "r"(addr));
}
__device__ __forceinline__ void ldsm4t(uint32_t addr, uint32_t r[4]) {
    asm volatile("ldmatrix.sync.aligned.m8n8.x4.trans.shared.b16 {%0,%1,%2,%3}, [%4];"
                 : "=r"(r[0]), "=r"(r[1]), "=r"(r[2]), "=r"(r[3]) : "r"(addr));
}
__device__ __forceinline__ void mma16816(float c[4], const uint32_t a[4], uint32_t b0, uint32_t b1) {
    asm volatile(
        "mma.sync.aligned.m16n8k16.row.col.f32.bf16.bf16.f32 "
        "{%0,%1,%2,%3}, {%4,%5,%6,%7}, {%8,%9}, {%0,%1,%2,%3};"
        : "+f"(c[0]), "+f"(c[1]), "+f"(c[2]), "+f"(c[3])
        : "r"(a[0]), "r"(a[1]), "r"(a[2]), "r"(a[3]), "r"(b0), "r"(b1));
}
__device__ __forceinline__ void split_bf(float x, __nv_bfloat16& h, __nv_bfloat16& l) {
    h = __float2bfloat16(x);
    l = __float2bfloat16(x - __bfloat162float(h));
}
__device__ __forceinline__ uint32_t pack2(__nv_bfloat16 a, __nv_bfloat16 b) {
    __nv_bfloat162 v = __halves2bfloat162(a, b);
    return *reinterpret_cast<uint32_t*>(&v);
}
__device__ __forceinline__ void split4(float4 f, uint2& hi, uint2& lo) {
    __nv_bfloat16 h0, l0, h1, l1, h2, l2, h3, l3;
    split_bf(f.x, h0, l0); split_bf(f.y, h1, l1);
    split_bf(f.z, h2, l2); split_bf(f.w, h3, l3);
    hi = make_uint2(pack2(h0, h1), pack2(h2, h3));
    lo = make_uint2(pack2(l0, l1), pack2(l2, l3));
}

// ---------------------------------------------------------------------------
// Kernel 1: KV_c = K_c^T V_c. A = K^T via trans-ldmatrix of row-major K[j][d],
// B = V^T via trans-ldmatrix of row-major V[j][e]. Warp quadrants 32x32.
// ---------------------------------------------------------------------------
#define K1_KH 0
#define K1_KL (1*TILE_B)
#define K1_VH (2*TILE_B)
#define K1_VL (3*TILE_B)
#define K1_SMEM (4*TILE_B)

__global__ __launch_bounds__(128) void kv_kernel(const float* __restrict__ kg,
                                                 const float* __restrict__ vg) {
    extern __shared__ char sm[];
    const uint32_t sb = smem_u32(sm);
    const int tid = threadIdx.x, w = tid >> 5, l = tid & 31;
    const int c = blockIdx.x, bh = blockIdx.y;

    const float* kp = kg + ((size_t)bh * TT + (size_t)c * CH) * DD;
    const float* vp = vg + ((size_t)bh * TT + (size_t)c * CH) * DD;

#pragma unroll
    for (int it = 0; it < 8; it++) {
        int idx = tid + it * 128;
        int j = idx >> 4, d0 = (idx & 15) * 4;
        uint2 hi, lo;
        split4(*(const float4*)(kp + (size_t)j * DD + d0), hi, lo);
        *(uint2*)(sm + K1_KH + (j * PIT + d0) * 2) = hi;
        *(uint2*)(sm + K1_KL + (j * PIT + d0) * 2) = lo;
        split4(*(const float4*)(vp + (size_t)j * DD + d0), hi, lo);
        *(uint2*)(sm + K1_VH + (j * PIT + d0) * 2) = hi;
        *(uint2*)(sm + K1_VL + (j * PIT + d0) * 2) = lo;
    }
    __syncthreads();

    const int m0 = (w & 1) * 32, n0 = (w >> 1) * 32;
    // trans-A: rows = k(j), cols = m(d)
    const uint32_t aOff = (((l & 7) + ((l >> 4) & 1) * 8) * PIT + m0 + (l & 8)) * 2;
    // trans-B: rows = k(j), cols = n(e)
    const uint32_t bOff = (((l & 7) + (l & 8)) * PIT + n0 + ((l >> 4) & 1) * 8) * 2;

    float acc[2][4][4] = {};
    const uint32_t aSel[3] = {K1_KH, K1_KH, K1_KL};
    const uint32_t bSel[3] = {K1_VH, K1_VL, K1_VH};
#pragma unroll
    for (int p = 0; p < 3; p++) {
        const uint32_t aB = sb + aSel[p] + aOff, bB = sb + bSel[p] + bOff;
#pragma unroll
        for (int ks = 0; ks < 4; ks++) {
            const uint32_t ko = ks * 16 * PIT * 2;
            uint32_t a0[4], a1[4], b0[4], b1[4];
            ldsm4t(aB + ko, a0);
            ldsm4t(aB + ko + 32, a1);   // m0+16 (cols +16 elems)
            ldsm4t(bB + ko, b0);
            ldsm4t(bB + ko + 32, b1);   // n0+16
            mma16816(acc[0][0], a0, b0[0], b0[1]); mma16816(acc[0][1], a0, b0[2], b0[3]);
            mma16816(acc[0][2], a0, b1[0], b1[1]); mma16816(acc[0][3], a0, b1[2], b1[3]);
            mma16816(acc[1][0], a1, b0[0], b0[1]); mma16816(acc[1][1], a1, b0[2], b0[3]);
            mma16816(acc[1][2], a1, b1[0], b1[1]); mma16816(acc[1][3], a1, b1[2], b1[3]);
        }
    }

    float* outp = g_state + ((size_t)(bh * NC + c)) * (DD * DD);
#pragma unroll
    for (int mi = 0; mi < 2; mi++)
#pragma unroll
        for (int ni = 0; ni < 4; ni++)
#pragma unroll
            for (int half = 0; half < 2; half++) {
                int d = m0 + mi * 16 + (l >> 2) + half * 8;
                int e = n0 + ni * 8 + 2 * (l & 3);
                *(float2*)(outp + (size_t)d * DD + e) =
                    make_float2(acc[mi][ni][2 * half], acc[mi][ni][2 * half + 1]);
            }
}

// ---------------------------------------------------------------------------
// Kernel 2: exclusive prefix over 32 chunk states per bh (fp32)
// ---------------------------------------------------------------------------
__global__ __launch_bounds__(256) void prefix_kernel() {
    const int e = blockIdx.x * 256 + threadIdx.x;
    const int bh = blockIdx.y;
    size_t base = (size_t)bh * NC * (DD * DD) + e;
    float run = 0.f;
#pragma unroll
    for (int c = 0; c < NC; c++) {
        float t = g_state[base + (size_t)c * (DD * DD)];
        g_state[base + (size_t)c * (DD * DD)] = run;
        run += t;
    }
}

// ---------------------------------------------------------------------------
// Kernel 3: P = tril(Q K^T); O = Q S + P V. Row-stripe warps (16 rows each),
// P lives in registers (acc layout == A-operand layout), causal MMA skipping.
// ---------------------------------------------------------------------------
#define K3_QH 0
#define K3_QL (1*TILE_B)
#define K3_KH (2*TILE_B)
#define K3_KL (3*TILE_B)
#define K3_VH (4*TILE_B)
#define K3_VL (5*TILE_B)
#define K3_SH (6*TILE_B)
#define K3_SL (7*TILE_B)
#define K3_SMEM (8*TILE_B)

__global__ __launch_bounds__(128) void out_kernel(const float* __restrict__ qg,
                                                  const float* __restrict__ kg,
                                                  const float* __restrict__ vg,
                                                  float* __restrict__ og) {
    extern __shared__ char sm[];
    const uint32_t sb = smem_u32(sm);
    const int tid = threadIdx.x, w = tid >> 5, l = tid & 31;
    const int c = blockIdx.x, bh = blockIdx.y;

    const float* qp = qg + ((size_t)bh * TT + (size_t)c * CH) * DD;
    const float* kp = kg + ((size_t)bh * TT + (size_t)c * CH) * DD;
    const float* vp = vg + ((size_t)bh * TT + (size_t)c * CH) * DD;
    const float* sp = g_state + ((size_t)(bh * NC + c)) * (DD * DD);

#pragma unroll
    for (int it = 0; it < 8; it++) {
        int idx = tid + it * 128;
        int r = idx >> 4, d0 = (idx & 15) * 4;
        const uint32_t so = (r * PIT + d0) * 2;
        uint2 hi, lo;
        split4(*(const float4*)(qp + (size_t)r * DD + d0), hi, lo);
        *(uint2*)(sm + K3_QH + so) = hi;  *(uint2*)(sm + K3_QL + so) = lo;
        split4(*(const float4*)(kp + (size_t)r * DD + d0), hi, lo);
        *(uint2*)(sm + K3_KH + so) = hi;  *(uint2*)(sm + K3_KL + so) = lo;
        split4(*(const float4*)(vp + (size_t)r * DD + d0), hi, lo);
        *(uint2*)(sm + K3_VH + so) = hi;  *(uint2*)(sm + K3_VL + so) = lo;
        split4(*(const float4*)(sp + (size_t)r * DD + d0), hi, lo);
        *(uint2*)(sm + K3_SH + so) = hi;  *(uint2*)(sm + K3_SL + so) = lo;
    }
    __syncthreads();

    const int m0 = w * 16;
    const int gid = l >> 2, tig = l & 3;
    // non-trans A (row-major [m][k])
    const uint32_t aOffN = ((m0 + (l & 15)) * PIT + ((l >> 4) << 3)) * 2;
    // non-trans B (row-major [n][k])
    const uint32_t bOffN = (((l & 7) + ((l & 16) >> 1)) * PIT + ((l >> 3) & 1) * 8) * 2;
    // trans B (row-major [k][n])
    const uint32_t bOffT = (((l & 7) + (l & 8)) * PIT + ((l >> 4) & 1) * 8) * 2;

    // ---- P = Q K^T (causal: only n-blocks j <= 16(w+1)) ----
    float accP[8][4] = {};
    {
        const uint32_t aS[3] = {K3_QH, K3_QH, K3_QL};
        const uint32_t bS[3] = {K3_KH, K3_KL, K3_KH};
#pragma unroll
        for (int p = 0; p < 3; p++) {
            const uint32_t aB = sb + aS[p] + aOffN, bB = sb + bS[p] + bOffN;
#pragma unroll
            for (int ks = 0; ks < 4; ks++) {
                uint32_t a[4];
                ldsm4(aB + ks * 32, a);
#pragma unroll
                for (int nb = 0; nb < 4; nb++)
                    if (nb <= w) {
                        uint32_t b[4];
                        ldsm4(bB + nb * 16 * PIT * 2 + ks * 32, b);
                        mma16816(accP[2 * nb],     a, b[0], b[1]);
                        mma16816(accP[2 * nb + 1], a, b[2], b[3]);
                    }
            }
        }
    }

    // ---- mask + in-register split to A-operand fragments ----
    uint32_t aPh[4][4], aPl[4][4];
    const int i0 = m0 + gid;
#pragma unroll
    for (int nb = 0; nb < 4; nb++)
        if (nb <= w) {
#pragma unroll
            for (int s2 = 0; s2 < 2; s2++) {
                const int j0 = 16 * nb + 8 * s2 + 2 * tig;
                float c0 = (j0     <= i0)     ? accP[2 * nb + s2][0] : 0.f;
                float c1 = (j0 + 1 <= i0)     ? accP[2 * nb + s2][1] : 0.f;
                float c2 = (j0     <= i0 + 8) ? accP[2 * nb + s2][2] : 0.f;
                float c3 = (j0 + 1 <= i0 + 8) ? accP[2 * nb + s2][3] : 0.f;
                __nv_bfloat16 h0, l0, h1, l1, h2, l2, h3, l3;
                split_bf(c0, h0, l0); split_bf(c1, h1, l1);
                split_bf(c2, h2, l2); split_bf(c3, h3, l3);
                aPh[nb][2 * s2]     = pack2(h0, h1);
                aPh[nb][2 * s2 + 1] = pack2(h2, h3);
                aPl[nb][2 * s2]     = pack2(l0, l1);
                aPl[nb][2 * s2 + 1] = pack2(l2, l3);
            }
        }

    // ---- O1 = Q @ S (B = S^T via trans loads of S[d][e]) ----
    float accO[8][4] = {};
    {
        const uint32_t aS[3] = {K3_QH, K3_QH, K3_QL};
        const uint32_t bS[3] = {K3_SH, K3_SL, K3_SH};
#pragma unroll
        for (int p = 0; p < 3; p++) {
            const uint32_t aB = sb + aS[p] + aOffN, bB = sb + bS[p] + bOffT;
#pragma unroll
            for (int ks = 0; ks < 4; ks++) {
                uint32_t a[4];
                ldsm4(aB + ks * 32, a);
#pragma unroll
                for (int nb = 0; nb < 4; nb++) {
                    uint32_t b[4];
                    ldsm4t(bB + ks * 16 * PIT * 2 + nb * 32, b);
                    mma16816(accO[2 * nb],     a, b[0], b[1]);
                    mma16816(accO[2 * nb + 1], a, b[2], b[3]);
                }
            }
        }
    }

    // ---- O2 += P @ V (A = register P, B = V^T trans; causal k-blocks only) ----
    {
#pragma unroll
        for (int p = 0; p < 3; p++) {
            const uint32_t bB = sb + (p == 1 ? K3_VL : K3_VH) + bOffT;
#pragma unroll
            for (int kb = 0; kb < 4; kb++)
                if (kb <= w) {
                    const uint32_t (&a)[4] = (p < 2) ? aPh[kb] : aPl[kb];
#pragma unroll
                    for (int nb = 0; nb < 4; nb++) {
                        uint32_t b[4];
                        ldsm4t(bB + kb * 16 * PIT * 2 + nb * 32, b);
                        mma16816(accO[2 * nb],     a, b[0], b[1]);
                        mma16816(accO[2 * nb + 1], a, b[2], b[3]);
                    }
                }
        }
    }

    // ---- store O ----
    float* op = og + ((size_t)bh * TT + (size_t)c * CH) * DD;
#pragma unroll
    for (int nb8 = 0; nb8 < 8; nb8++) {
        const int e = 8 * nb8 + 2 * tig;
        *(float2*)(op + (size_t)i0 * DD + e)       = make_float2(accO[nb8][0], accO[nb8][1]);
        *(float2*)(op + (size_t)(i0 + 8) * DD + e) = make_float2(accO[nb8][2], accO[nb8][3]);
    }
}

// ---------------------------------------------------------------------------
extern "C" void kernel_launch(void* const* d_in, const int* in_sizes, int n_in,
                              void* d_out, int out_size) {
    const float* q = (const float*)d_in[0];
    const float* k = (const float*)d_in[1];
    const float* v = (const float*)d_in[2];
    float* o = (float*)d_out;

    cudaFuncSetAttribute(kv_kernel, cudaFuncAttributeMaxDynamicSharedMemorySize, K1_SMEM);
    cudaFuncSetAttribute(out_kernel, cudaFuncAttributeMaxDynamicSharedMemorySize, K3_SMEM);

    dim3 grid(NC, BH);
    kv_kernel<<<grid, 128, K1_SMEM>>>(k, v);
    prefix_kernel<<<dim3((DD * DD) / 256, BH), 256>>>();
    out_kernel<<<grid, 128, K3_SMEM>>>(q, k, v, o);
}